// round 5
// baseline (speedup 1.0000x reference)
#include <cuda_runtime.h>
#include <math.h>
#include <math_constants.h>

#define BS 16
#define Q 900
#define NC 92
#define T 100
#define NT (BS * T)   // 1600
#define QPB 4         // q per block in cost kernel (900 % 4 == 0 -> 225 blocks/batch)
#define NK 29         // columns per lane in LSA (32 * 29 = 928 >= 901)

// Transposed per-batch cost slice: ct[b][t][q] = C[b, q, b*T + t]
__device__ float g_ct[BS][T][Q];

// ---------------------------------------------------------------------------
// Kernel 1: cost matrix. One warp per q row; 4 q per block.
// ---------------------------------------------------------------------------
__global__ void __launch_bounds__(128) cost_kernel(
    const float* __restrict__ logits,   // [BS*Q, NC]
    const float* __restrict__ pboxes,   // [BS*Q, 4]  cxcywh
    const int*   __restrict__ tgt_ids,  // [NT]
    const float* __restrict__ tbox,     // [NT, 4]    xyxy
    float* __restrict__ C)              // [BS*Q, NT]
{
    const int b     = blockIdx.x / (Q / QPB);
    const int qbase = (blockIdx.x % (Q / QPB)) * QPB;
    const int lane  = threadIdx.x & 31;
    const int w     = threadIdx.x >> 5;      // 0..3
    const int q     = qbase + w;
    const int bq    = b * Q + q;

    __shared__ float sp[QPB][NC];     // per-warp softmax probs
    __shared__ float tile[T][QPB];    // own-batch costs for transpose write

    // per-warp softmax over 92 logits
    const float* L = logits + (size_t)bq * NC;
    float l0 = (lane      < NC) ? __ldg(L + lane)      : -CUDART_INF_F;
    float l1 = (lane + 32 < NC) ? __ldg(L + lane + 32) : -CUDART_INF_F;
    float l2 = (lane + 64 < NC) ? __ldg(L + lane + 64) : -CUDART_INF_F;

    float m = fmaxf(l0, fmaxf(l1, l2));
    #pragma unroll
    for (int o = 16; o; o >>= 1) m = fmaxf(m, __shfl_xor_sync(0xffffffffu, m, o));

    float e0 = (lane      < NC) ? expf(l0 - m) : 0.f;
    float e1 = (lane + 32 < NC) ? expf(l1 - m) : 0.f;
    float e2 = (lane + 64 < NC) ? expf(l2 - m) : 0.f;
    float s = e0 + e1 + e2;
    #pragma unroll
    for (int o = 16; o; o >>= 1) s += __shfl_xor_sync(0xffffffffu, s, o);
    const float inv_s = 1.0f / s;

    if (lane      < NC) sp[w][lane]      = e0 * inv_s;
    if (lane + 32 < NC) sp[w][lane + 32] = e1 * inv_s;
    if (lane + 64 < NC) sp[w][lane + 64] = e2 * inv_s;
    __syncwarp();

    const float cx = pboxes[bq * 4 + 0];
    const float cy = pboxes[bq * 4 + 1];
    const float wd = pboxes[bq * 4 + 2];
    const float ht = pboxes[bq * 4 + 3];
    const float px0 = cx - wd * 0.5f, py0 = cy - ht * 0.5f;
    const float px1 = cx + wd * 0.5f, py1 = cy + ht * 0.5f;
    const float area_a = (px1 - px0) * (py1 - py0);

    float* Crow = C + (size_t)bq * NT;
    const float4* tb4 = reinterpret_cast<const float4*>(tbox);

    #pragma unroll 2
    for (int j = lane; j < NT; j += 32) {
        const int id = __ldg(tgt_ids + j);
        const float prob = sp[w][id];

        const float4 tb = __ldg(tb4 + j);
        const float tx0 = tb.x, ty0 = tb.y, tx1 = tb.z, ty1 = tb.w;

        const float tcx = (tx0 + tx1) * 0.5f, tcy = (ty0 + ty1) * 0.5f;
        const float tw  = tx1 - tx0,          th  = ty1 - ty0;

        const float cb = fabsf(cx - tcx) + fabsf(cy - tcy) + fabsf(wd - tw) + fabsf(ht - th);

        const float area_b = tw * th;
        const float ltx = fmaxf(px0, tx0), lty = fmaxf(py0, ty0);
        const float rbx = fminf(px1, tx1), rby = fminf(py1, ty1);
        const float iw = fmaxf(rbx - ltx, 0.f), ih = fmaxf(rby - lty, 0.f);
        const float inter = iw * ih;
        const float uni = area_a + area_b - inter;
        const float iou = inter / uni;
        const float lcx = fminf(px0, tx0), lcy = fminf(py0, ty0);
        const float rcx = fmaxf(px1, tx1), rcy = fmaxf(py1, ty1);
        const float cw = fmaxf(rcx - lcx, 0.f), ch = fmaxf(rcy - lcy, 0.f);
        const float ac = cw * ch;
        const float giou = iou - (ac - uni) / ac;

        float cost = 5.0f * cb + (-prob);
        cost = cost + 2.0f * (-giou);

        Crow[j] = cost;

        const int tl = j - b * T;
        if (tl >= 0 && tl < T) tile[tl][w] = cost;
    }
    __syncthreads();

    // transpose write: g_ct[b][t][qbase..qbase+3] as one float4 per t
    if (threadIdx.x < T) {
        const int t = threadIdx.x;
        float4 v4 = *reinterpret_cast<const float4*>(&tile[t][0]);
        *reinterpret_cast<float4*>(&g_ct[b][t][qbase]) = v4;
    }
}

// ---------------------------------------------------------------------------
// Kernel 2: Jonker-Volgenant LSA, ONE WARP per batch. 29 columns per lane,
// used-set as a 29-bit register mask, zero block barriers.
// ---------------------------------------------------------------------------
__device__ __forceinline__ void amin_combine(float& v, int& i, float v2, int i2) {
    if (v2 < v || (v2 == v && i2 < i)) { v = v2; i = i2; }
}

__global__ void __launch_bounds__(32) lsa_kernel(
    float* __restrict__ rows_out,   // [BS*T]
    float* __restrict__ cols_out)   // [BS*T]
{
    const int b    = blockIdx.x;
    const int lane = threadIdx.x;

    __shared__ float u[T + 1];
    __shared__ int   p[Q + 1];
    __shared__ int   sway[Q + 1];
    __shared__ int   ans[T];

    for (int k = lane; k <= T; k += 32) u[k] = 0.f;
    for (int k = lane; k <= Q; k += 32) p[k] = 0;

    float v[NK];       // column duals (persist across rows)
    float minv[NK];
    #pragma unroll
    for (int k = 0; k < NK; ++k) v[k] = 0.f;
    __syncwarp();

    for (int i = 1; i <= T; ++i) {
        #pragma unroll
        for (int k = 0; k < NK; ++k) minv[k] = CUDART_INF_F;
        unsigned usedmask = 0;
        if (lane == 0) p[0] = i;

        int   j0   = 0;
        int   i0   = i;
        float u_i0 = u[i];
        __syncwarp();

        while (true) {
            const float* crow = &g_ct[b][i0 - 1][0];

            float bestv = CUDART_INF_F;
            int   besti = 0x7FFFFFF0;
            #pragma unroll
            for (int k = 0; k < NK; ++k) {
                const int jc = 1 + lane + 32 * k;
                if (jc == j0) usedmask |= (1u << k);
                if (jc <= Q && !(usedmask & (1u << k))) {
                    const float cur = __ldg(crow + (jc - 1)) - u_i0 - v[k];
                    if (cur < minv[k]) { minv[k] = cur; sway[jc] = j0; }
                    if (minv[k] < bestv) { bestv = minv[k]; besti = jc; }
                }
            }

            // warp argmin with first-index tiebreak (np.argmin semantics)
            #pragma unroll
            for (int o = 16; o; o >>= 1) {
                const float v2 = __shfl_xor_sync(0xffffffffu, bestv, o);
                const int   i2 = __shfl_xor_sync(0xffffffffu, besti, o);
                amin_combine(bestv, besti, v2, i2);
            }
            const float delta = bestv;   // all lanes hold the reduction result
            const int   j1    = besti;

            // dual updates: used columns' rows += delta, others' minv -= delta
            #pragma unroll
            for (int k = 0; k < NK; ++k) {
                const int jc = 1 + lane + 32 * k;
                if (jc <= Q) {
                    if (usedmask & (1u << k)) { u[p[jc]] += delta; v[k] -= delta; }
                    else                        minv[k] -= delta;
                }
            }
            if (lane == 0) u[i] += delta;   // virtual column j0=0: p[0] = i
            __syncwarp();

            j0   = j1;
            i0   = p[j1];                    // row of j1: not in this update set
            u_i0 = u[i0];
            if (i0 == 0) break;
        }

        // augment (serial walk, short)
        if (lane == 0) {
            int j0a = j0;
            while (j0a) {
                const int j1a = sway[j0a];
                p[j0a] = p[j1a];
                j0a = j1a;
            }
        }
        __syncwarp();
    }

    // extract: ans[t] = pred column assigned to target t
    #pragma unroll
    for (int k = 0; k < NK; ++k) {
        const int jc = 1 + lane + 32 * k;
        if (jc <= Q) {
            const int r = p[jc];
            if (r > 0) ans[r - 1] = jc - 1;
        }
    }
    __syncwarp();

    // rows = sorted pred indices, cols = targets ordered by their pred index
    for (int t = lane; t < T; t += 32) {
        const int a = ans[t];
        int rank = 0;
        #pragma unroll 4
        for (int tt = 0; tt < T; ++tt) rank += (ans[tt] < a);
        rows_out[b * T + rank] = (float)a;
        cols_out[b * T + rank] = (float)t;
    }
}

// ---------------------------------------------------------------------------
extern "C" void kernel_launch(void* const* d_in, const int* in_sizes, int n_in,
                              void* d_out, int out_size) {
    const float* logits = (const float*)d_in[0];
    const float* pboxes = (const float*)d_in[1];
    const int*   ids    = (const int*)d_in[2];
    const float* tbox   = (const float*)d_in[3];
    float* out = (float*)d_out;

    const long long CN = (long long)BS * Q * NT;   // 23,040,000

    cost_kernel<<<BS * (Q / QPB), 128>>>(logits, pboxes, ids, tbox, out);

    if ((long long)out_size >= CN + 2LL * BS * T) {
        lsa_kernel<<<BS, 32>>>(out + CN, out + CN + (long long)BS * T);
    }
}

// round 6
// speedup vs baseline: 3.7648x; 3.7648x over previous
#include <cuda_runtime.h>
#include <math.h>
#include <math_constants.h>

#define BS 16
#define Q 900
#define NC 92
#define T 100
#define NT (BS * T)   // 1600
#define NK 29         // columns per lane in LSA (32*29 = 928)
#define QP (32 * NK)  // padded row stride = 928

// Transposed per-batch cost slice, padded: ct[b][t][0..899]=cost, [900..927]=+INF
__device__ float g_ct[BS][T][QP];

// ---------------------------------------------------------------------------
// Kernel 1: cost matrix (R4 version, measured ~84us) + INF pad writes.
// ---------------------------------------------------------------------------
__global__ void __launch_bounds__(256) cost_kernel(
    const float* __restrict__ logits,   // [BS*Q, NC]
    const float* __restrict__ pboxes,   // [BS*Q, 4]  cxcywh
    const int*   __restrict__ tgt_ids,  // [NT]
    const float* __restrict__ tbox,     // [NT, 4]    xyxy
    float* __restrict__ C)              // [BS*Q, NT]
{
    const int bq  = blockIdx.x;
    const int b   = bq / Q;
    const int q   = bq - b * Q;
    const int tid = threadIdx.x;

    __shared__ float sl[NC];
    __shared__ float sp[NC];
    __shared__ float smax, ssum;

    const float* L = logits + (size_t)bq * NC;
    if (tid < NC) sl[tid] = L[tid];
    __syncthreads();

    if (tid < 32) {
        float m = -CUDART_INF_F;
        for (int c = tid; c < NC; c += 32) m = fmaxf(m, sl[c]);
        #pragma unroll
        for (int o = 16; o; o >>= 1) m = fmaxf(m, __shfl_xor_sync(0xffffffffu, m, o));
        float s = 0.f;
        for (int c = tid; c < NC; c += 32) s += expf(sl[c] - m);
        #pragma unroll
        for (int o = 16; o; o >>= 1) s += __shfl_xor_sync(0xffffffffu, s, o);
        if (tid == 0) { smax = m; ssum = s; }
    }
    __syncthreads();

    if (tid < NC) sp[tid] = expf(sl[tid] - smax) / ssum;
    __syncthreads();

    const float cx = pboxes[bq * 4 + 0];
    const float cy = pboxes[bq * 4 + 1];
    const float w  = pboxes[bq * 4 + 2];
    const float h  = pboxes[bq * 4 + 3];
    const float px0 = cx - w * 0.5f, py0 = cy - h * 0.5f;
    const float px1 = cx + w * 0.5f, py1 = cy + h * 0.5f;
    const float area_a = (px1 - px0) * (py1 - py0);

    float* Crow = C + (size_t)bq * NT;
    const float4* tb4 = reinterpret_cast<const float4*>(tbox);

    for (int j = tid; j < NT; j += 256) {
        const int id = __ldg(tgt_ids + j);
        const float prob = sp[id];

        const float4 tb = __ldg(tb4 + j);
        const float tx0 = tb.x, ty0 = tb.y, tx1 = tb.z, ty1 = tb.w;

        const float tcx = (tx0 + tx1) * 0.5f, tcy = (ty0 + ty1) * 0.5f;
        const float tw  = tx1 - tx0,          th  = ty1 - ty0;

        const float cb = fabsf(cx - tcx) + fabsf(cy - tcy) + fabsf(w - tw) + fabsf(h - th);

        const float area_b = tw * th;
        const float ltx = fmaxf(px0, tx0), lty = fmaxf(py0, ty0);
        const float rbx = fminf(px1, tx1), rby = fminf(py1, ty1);
        const float iw = fmaxf(rbx - ltx, 0.f), ih = fmaxf(rby - lty, 0.f);
        const float inter = iw * ih;
        const float uni = area_a + area_b - inter;
        const float iou = inter / uni;
        const float lcx = fminf(px0, tx0), lcy = fminf(py0, ty0);
        const float rcx = fmaxf(px1, tx1), rcy = fmaxf(py1, ty1);
        const float cw = fmaxf(rcx - lcx, 0.f), ch = fmaxf(rcy - lcy, 0.f);
        const float ac = cw * ch;
        const float giou = iou - (ac - uni) / ac;

        float cost = 5.0f * cb + (-prob);
        cost = cost + 2.0f * (-giou);

        Crow[j] = cost;

        const int tl = j - b * T;
        if (tl >= 0 && tl < T) g_ct[b][tl][q] = cost;
    }

    // pad columns [900..927] with +INF (one block per batch does it)
    if (q == 0) {
        for (int idx = tid; idx < T * (QP - Q); idx += 256) {
            const int t = idx / (QP - Q);
            const int c = idx - t * (QP - Q);
            g_ct[b][t][Q + c] = CUDART_INF_F;
        }
    }
}

// ---------------------------------------------------------------------------
// Kernel 2: Jonker-Volgenant LSA, ONE WARP per batch. Branch-free batched row
// scan: 29 unconditional LDGs per lane (MLP=29), select-based used masking.
// ---------------------------------------------------------------------------
__device__ __forceinline__ void amin_combine(float& v, int& i, float v2, int i2) {
    if (v2 < v || (v2 == v && i2 < i)) { v = v2; i = i2; }
}

__global__ void __launch_bounds__(32) lsa_kernel(
    float* __restrict__ rows_out,   // [BS*T]
    float* __restrict__ cols_out)   // [BS*T]
{
    const int b    = blockIdx.x;
    const int lane = threadIdx.x;

    __shared__ float u[T + 1];
    __shared__ int   p[QP + 1];
    __shared__ int   sway[QP + 1];
    __shared__ int   ans[T];

    for (int k = lane; k <= T; k += 32) u[k] = 0.f;
    for (int k = lane; k <= QP; k += 32) p[k] = 0;

    float v[NK];       // column duals
    float minv[NK];
    #pragma unroll
    for (int k = 0; k < NK; ++k) v[k] = 0.f;
    __syncwarp();

    for (int i = 1; i <= T; ++i) {
        #pragma unroll
        for (int k = 0; k < NK; ++k) minv[k] = CUDART_INF_F;
        unsigned usedmask = 0;
        if (lane == 0) p[0] = i;

        int   j0   = 0;
        int   i0   = i;
        float u_i0 = u[i];
        __syncwarp();

        while (true) {
            // mark j0 used (at most one k per lane matches)
            {
                const int d = j0 - 1 - lane;
                if (d >= 0 && (d & 31) == 0) usedmask |= (1u << (d >> 5));
            }

            // batched unconditional loads of the whole (padded) row
            const float* crow = &g_ct[b][i0 - 1][0];
            float val[NK];
            #pragma unroll
            for (int k = 0; k < NK; ++k) val[k] = __ldg(crow + lane + 32 * k);

            const float neg = -u_i0;
            float bestv = CUDART_INF_F;
            int   besti = 0x7FFFFFF0;
            #pragma unroll
            for (int k = 0; k < NK; ++k) {
                const int  jc     = 1 + lane + 32 * k;
                const bool isused = (usedmask >> k) & 1u;
                float cur = (val[k] + neg) - v[k];
                cur = isused ? CUDART_INF_F : cur;
                if (cur < minv[k]) { minv[k] = cur; sway[jc] = j0; }  // predicated
                const float mk = isused ? CUDART_INF_F : minv[k];
                if (mk < bestv) { bestv = mk; besti = jc; }
            }

            // warp argmin, first-index tiebreak (np.argmin semantics)
            #pragma unroll
            for (int o = 16; o; o >>= 1) {
                const float v2 = __shfl_xor_sync(0xffffffffu, bestv, o);
                const int   i2 = __shfl_xor_sync(0xffffffffu, besti, o);
                amin_combine(bestv, besti, v2, i2);
            }
            const float delta = bestv;
            const int   j1    = besti;

            // dual updates (exact reference order/arithmetic)
            #pragma unroll
            for (int k = 0; k < NK; ++k) {
                const int jc = 1 + lane + 32 * k;
                if ((usedmask >> k) & 1u) { u[p[jc]] += delta; v[k] -= delta; }
                minv[k] -= delta;   // stale for used cols; they're masked anyway
            }
            if (lane == 0) u[i] += delta;   // virtual column j0=0 (p[0]=i)
            __syncwarp();

            j0   = j1;
            i0   = p[j1];          // j1's row: not in this iteration's update set
            u_i0 = u[i0];
            if (i0 == 0) break;
        }

        // augment (serial walk, short)
        __syncwarp();
        if (lane == 0) {
            int j0a = j0;
            while (j0a) {
                const int j1a = sway[j0a];
                p[j0a] = p[j1a];
                j0a = j1a;
            }
        }
        __syncwarp();
    }

    // extract: ans[t] = pred column assigned to target t
    #pragma unroll
    for (int k = 0; k < NK; ++k) {
        const int jc = 1 + lane + 32 * k;
        if (jc <= Q) {
            const int r = p[jc];
            if (r > 0) ans[r - 1] = jc - 1;
        }
    }
    __syncwarp();

    // rows = sorted pred indices, cols = targets ordered by their pred index
    for (int t = lane; t < T; t += 32) {
        const int a = ans[t];
        int rank = 0;
        #pragma unroll 4
        for (int tt = 0; tt < T; ++tt) rank += (ans[tt] < a);
        rows_out[b * T + rank] = (float)a;
        cols_out[b * T + rank] = (float)t;
    }
}

// ---------------------------------------------------------------------------
extern "C" void kernel_launch(void* const* d_in, const int* in_sizes, int n_in,
                              void* d_out, int out_size) {
    const float* logits = (const float*)d_in[0];
    const float* pboxes = (const float*)d_in[1];
    const int*   ids    = (const int*)d_in[2];
    const float* tbox   = (const float*)d_in[3];
    float* out = (float*)d_out;

    const long long CN = (long long)BS * Q * NT;   // 23,040,000

    cost_kernel<<<BS * Q, 256>>>(logits, pboxes, ids, tbox, out);

    if ((long long)out_size >= CN + 2LL * BS * T) {
        lsa_kernel<<<BS, 32>>>(out + CN, out + CN + (long long)BS * T);
    }
}

// round 7
// speedup vs baseline: 6.2301x; 1.6548x over previous
#include <cuda_runtime.h>
#include <math.h>
#include <math_constants.h>

#define BS 16
#define Q 900
#define NC 92
#define T 100
#define NT (BS * T)   // 1600

#define CQB 12        // q's (=warps) per cost block; Q/CQB = 75
#define LTH 256       // lsa threads
#define LNK 4         // cols per thread in lsa
#define QP 1024       // padded row stride (256*4)

// Transposed per-batch cost slice, padded: ct[b][t][0..899]=cost, [900..1023]=+INF
__device__ float g_ct[BS][T][QP];

// ---------------------------------------------------------------------------
// Kernel 1: cost matrix. 12 warps/block, one q per warp, targets staged in smem.
// ---------------------------------------------------------------------------
__global__ void __launch_bounds__(32 * CQB) cost_kernel(
    const float* __restrict__ logits,   // [BS*Q, NC]
    const float* __restrict__ pboxes,   // [BS*Q, 4]  cxcywh
    const int*   __restrict__ tgt_ids,  // [NT]
    const float* __restrict__ tbox,     // [NT, 4]    xyxy
    float* __restrict__ C)              // [BS*Q, NT]
{
    const int b     = blockIdx.x / (Q / CQB);
    const int qbase = (blockIdx.x % (Q / CQB)) * CQB;
    const int tid   = threadIdx.x;
    const int lane  = tid & 31;
    const int w     = tid >> 5;          // 0..11
    const int q     = qbase + w;
    const int bq    = b * Q + q;

    __shared__ float4 s_xy[NT];          // target xyxy
    __shared__ int    s_id[NT];          // target class ids
    __shared__ float  sp[CQB][NC];       // per-warp softmax probs

    // stage targets once per block
    const float4* tb4 = reinterpret_cast<const float4*>(tbox);
    for (int j = tid; j < NT; j += 32 * CQB) {
        s_xy[j] = __ldg(tb4 + j);
        s_id[j] = __ldg(tgt_ids + j);
    }

    // per-warp softmax over 92 logits
    const float* L = logits + (size_t)bq * NC;
    float l0 = (lane      < NC) ? __ldg(L + lane)      : -CUDART_INF_F;
    float l1 = (lane + 32 < NC) ? __ldg(L + lane + 32) : -CUDART_INF_F;
    float l2 = (lane + 64 < NC) ? __ldg(L + lane + 64) : -CUDART_INF_F;

    float m = fmaxf(l0, fmaxf(l1, l2));
    #pragma unroll
    for (int o = 16; o; o >>= 1) m = fmaxf(m, __shfl_xor_sync(0xffffffffu, m, o));

    float e0 = (lane      < NC) ? expf(l0 - m) : 0.f;
    float e1 = (lane + 32 < NC) ? expf(l1 - m) : 0.f;
    float e2 = (lane + 64 < NC) ? expf(l2 - m) : 0.f;
    float s = e0 + e1 + e2;
    #pragma unroll
    for (int o = 16; o; o >>= 1) s += __shfl_xor_sync(0xffffffffu, s, o);
    const float inv_s = 1.0f / s;

    if (lane      < NC) sp[w][lane]      = e0 * inv_s;
    if (lane + 32 < NC) sp[w][lane + 32] = e1 * inv_s;
    if (lane + 64 < NC) sp[w][lane + 64] = e2 * inv_s;
    __syncthreads();

    const float cx = pboxes[bq * 4 + 0];
    const float cy = pboxes[bq * 4 + 1];
    const float wd = pboxes[bq * 4 + 2];
    const float ht = pboxes[bq * 4 + 3];
    const float px0 = cx - wd * 0.5f, py0 = cy - ht * 0.5f;
    const float px1 = cx + wd * 0.5f, py1 = cy + ht * 0.5f;
    const float area_a = (px1 - px0) * (py1 - py0);

    float* Crow = C + (size_t)bq * NT;

    for (int j = lane; j < NT; j += 32) {
        const float prob = sp[w][s_id[j]];

        const float4 tb = s_xy[j];
        const float tx0 = tb.x, ty0 = tb.y, tx1 = tb.z, ty1 = tb.w;

        const float tcx = (tx0 + tx1) * 0.5f, tcy = (ty0 + ty1) * 0.5f;
        const float tw  = tx1 - tx0,          th  = ty1 - ty0;

        const float cb = fabsf(cx - tcx) + fabsf(cy - tcy) + fabsf(wd - tw) + fabsf(ht - th);

        const float area_b = tw * th;
        const float ltx = fmaxf(px0, tx0), lty = fmaxf(py0, ty0);
        const float rbx = fminf(px1, tx1), rby = fminf(py1, ty1);
        const float iw = fmaxf(rbx - ltx, 0.f), ih = fmaxf(rby - lty, 0.f);
        const float inter = iw * ih;
        const float uni = area_a + area_b - inter;
        const float iou = inter / uni;
        const float lcx = fminf(px0, tx0), lcy = fminf(py0, ty0);
        const float rcx = fmaxf(px1, tx1), rcy = fmaxf(py1, ty1);
        const float cw = fmaxf(rcx - lcx, 0.f), ch = fmaxf(rcy - lcy, 0.f);
        const float ac = cw * ch;
        const float giou = iou - (ac - uni) / ac;

        float cost = 5.0f * cb + (-prob);
        cost = cost + 2.0f * (-giou);

        Crow[j] = cost;
    }
}

// ---------------------------------------------------------------------------
// Kernel 2: smem-tiled transpose C -> g_ct (own-batch slice) + INF padding.
// Runs after the big C stream so g_ct ends up hot in L2.
// ---------------------------------------------------------------------------
__global__ void __launch_bounds__(256) transpose_kernel(const float* __restrict__ C)
{
    const int b  = blockIdx.y;
    const int q0 = blockIdx.x * 32;      // 32 tiles cover q in [0,1024)
    const int tx = threadIdx.x;          // 32
    const int ty = threadIdx.y;          // 8

    __shared__ float tile[32][33];

    #pragma unroll
    for (int t0 = 0; t0 < T; t0 += 32) {
        // read: rows=q, cols=t (coalesced in t)
        for (int r = ty; r < 32; r += 8) {
            const int q = q0 + r;
            const int t = t0 + tx;
            float v = 0.f;
            if (q < Q && t < T)
                v = __ldg(C + (size_t)(b * Q + q) * NT + b * T + t);
            tile[r][tx] = v;
        }
        __syncthreads();
        // write: rows=t, cols=q (coalesced in q)
        for (int r = ty; r < 32; r += 8) {
            const int t = t0 + r;
            if (t < T) {
                const int q = q0 + tx;
                g_ct[b][t][q] = (q < Q) ? tile[tx][r] : CUDART_INF_F;
            }
        }
        __syncthreads();
    }
}

// ---------------------------------------------------------------------------
// Kernel 3: JV LSA, 256 threads per batch. Mono-u32 keys, REDUX warp argmin,
// delta-accumulator (no minv rewrite), 1 barrier/iter, next-row prefetch.
// ---------------------------------------------------------------------------
__global__ void __launch_bounds__(LTH) lsa_kernel(
    float* __restrict__ rows_out,   // [BS*T]
    float* __restrict__ cols_out)   // [BS*T]
{
    const int b    = blockIdx.x;
    const int tid  = threadIdx.x;
    const int lane = tid & 31;
    const int wid  = tid >> 5;

    __shared__ float u[T + 1];
    __shared__ int   p[QP + 1];
    __shared__ int   sway[QP + 1];
    __shared__ int   ans[T];
    __shared__ unsigned long long red[2][8];

    for (int k = tid; k <= T;  k += LTH) u[k] = 0.f;
    for (int k = tid; k <= QP; k += LTH) p[k] = 0;

    float    v[LNK];
    unsigned minm[LNK];
    float    val[LNK];
    #pragma unroll
    for (int k = 0; k < LNK; ++k) v[k] = 0.f;
    __syncthreads();

    const float* base = &g_ct[b][0][0];
    int itpar = 0;

    for (int i = 1; i <= T; ++i) {
        #pragma unroll
        for (int k = 0; k < LNK; ++k) minm[k] = 0xFFFFFFFFu;
        unsigned usedmask = 0;
        if (tid == 0) p[0] = i;

        int   j0   = 0;
        float u_i0 = u[i];
        float D    = 0.f;

        // prefetch root row
        {
            const float* crow = base + (size_t)(i - 1) * QP;
            #pragma unroll
            for (int k = 0; k < LNK; ++k) val[k] = __ldg(crow + tid + LTH * k);
        }

        while (true) {
            // mark j0 used (at most one thread/k matches)
            {
                const int d = j0 - 1 - tid;
                if (d >= 0 && (d & (LTH - 1)) == 0) usedmask |= 1u << (d >> 8);
            }

            const float adj = u_i0 - D;
            unsigned wmin = 0xFFFFFFFFu;
            unsigned mk[LNK];
            #pragma unroll
            for (int k = 0; k < LNK; ++k) {
                const int jc = 1 + tid + LTH * k;
                const float curf = (val[k] - adj) - v[k];
                const unsigned cu = __float_as_uint(curf);
                const unsigned cm = (cu & 0x80000000u) ? ~cu : (cu | 0x80000000u);
                const bool isused = (usedmask >> k) & 1u;
                if (!isused && cm < minm[k]) { minm[k] = cm; sway[jc] = j0; }
                mk[k] = isused ? 0xFFFFFFFFu : minm[k];
                wmin = umin(wmin, mk[k]);
            }
            const unsigned wbest = __reduce_min_sync(0xffffffffu, wmin);

            unsigned idxc = 0x7FFFFFFFu;
            #pragma unroll
            for (int k = 0; k < LNK; ++k) {
                const int jc = 1 + tid + LTH * k;
                if (mk[k] == wbest) idxc = umin(idxc, (unsigned)jc);
            }
            const unsigned widx = __reduce_min_sync(0xffffffffu, idxc);

            if (lane == 0)
                red[itpar][wid] = ((unsigned long long)wbest << 32) | widx;
            __syncthreads();                                   // the ONE barrier

            unsigned long long bk = red[itpar][0];
            #pragma unroll
            for (int ww = 1; ww < 8; ++ww) {
                const unsigned long long c2 = red[itpar][ww];
                if (c2 < bk) bk = c2;
            }
            itpar ^= 1;

            const unsigned bm = (unsigned)(bk >> 32);
            const int      j1 = (int)(unsigned)bk;

            // next row + early prefetch (row i0n's u and c-row are NOT touched
            // by this iteration's updates)
            const int i0n = p[j1];
            if (i0n) {
                const float* nrow = base + (size_t)(i0n - 1) * QP;
                #pragma unroll
                for (int k = 0; k < LNK; ++k) val[k] = __ldg(nrow + tid + LTH * k);
            }

            const unsigned ub = (bm & 0x80000000u) ? (bm ^ 0x80000000u) : ~bm;
            const float delta_raw = __uint_as_float(ub);
            const float delta = delta_raw - D;
            D = delta_raw;

            // sparse dual updates (distinct rows per used column -> race-free)
            unsigned mm = usedmask;
            while (mm) {
                const int k = __ffs(mm) - 1; mm &= mm - 1;
                const int jc = 1 + tid + LTH * k;
                u[p[jc]] += delta;
                v[k] -= delta;
            }
            if (tid == 0) u[i] += delta;     // virtual column 0 (p[0] = i)

            j0 = j1;
            if (!i0n) break;
            u_i0 = u[i0n];
        }

        __syncthreads();   // sway/u settled before augment
        if (tid == 0) {
            int j0a = j0;
            while (j0a) {
                const int j1a = sway[j0a];
                p[j0a] = p[j1a];
                j0a = j1a;
            }
        }
        __syncthreads();   // p settled before next phase
    }

    // extract: ans[t] = pred column assigned to target t
    for (int jc = 1 + tid; jc <= Q; jc += LTH) {
        const int r = p[jc];
        if (r > 0) ans[r - 1] = jc - 1;
    }
    __syncthreads();

    // rows = sorted pred indices, cols = targets ordered by their pred index
    if (tid < T) {
        const int a = ans[tid];
        int rank = 0;
        #pragma unroll 4
        for (int tt = 0; tt < T; ++tt) rank += (ans[tt] < a);
        rows_out[b * T + rank] = (float)a;
        cols_out[b * T + rank] = (float)tid;
    }
}

// ---------------------------------------------------------------------------
extern "C" void kernel_launch(void* const* d_in, const int* in_sizes, int n_in,
                              void* d_out, int out_size) {
    const float* logits = (const float*)d_in[0];
    const float* pboxes = (const float*)d_in[1];
    const int*   ids    = (const int*)d_in[2];
    const float* tbox   = (const float*)d_in[3];
    float* out = (float*)d_out;

    const long long CN = (long long)BS * Q * NT;   // 23,040,000

    cost_kernel<<<BS * (Q / CQB), 32 * CQB>>>(logits, pboxes, ids, tbox, out);

    dim3 tgrid(32, BS);
    dim3 tblk(32, 8);
    transpose_kernel<<<tgrid, tblk>>>(out);

    if ((long long)out_size >= CN + 2LL * BS * T) {
        lsa_kernel<<<BS, LTH>>>(out + CN, out + CN + (long long)BS * T);
    }
}